// round 1
// baseline (speedup 1.0000x reference)
#include <cuda_runtime.h>
#include <cuda_bf16.h>
#include <cstdint>

#define BB 8
#define NN 20000
#define GG 300
#define CC 80
#define KK 4
#define MAXPOS 128
#define T_HIGH_F 0.7f

// Monotone encoding of float for unsigned atomicMax / exact-equality compare.
// enc(-1.0f) = 0x407FFFFF, enc(0.0f) = 0x80000000.
#define ENC_NEG1 0x407FFFFFu
#define ENC_ZERO 0x80000000u

__device__ __forceinline__ unsigned encf(float f) {
    unsigned u = __float_as_uint(f);
    return (u & 0x80000000u) ? ~u : (u | 0x80000000u);
}

// ---------------- device scratch (no allocations allowed) ----------------
__device__ float4   g_gt_xyxy[BB * GG];
__device__ float    g_gt_area[BB * GG];
__device__ int      g_gt_cls_start[BB * (CC + 1)];
__device__ int      g_gt_cls_list[BB * GG];
__device__ unsigned g_gt_max[BB * GG];       // encoded float max per gt row
__device__ int      g_counts[BB * GG];       // subsampled positives per gt
__device__ float    g_anchor_max[BB * NN];
__device__ int      g_anchor_gt[BB * NN];
__device__ unsigned char g_pos[BB * NN];
__device__ int      g_bin_cursor[BB * CC];   // anchors per (b, class)
__device__ int      g_poscnt[BB * CC];       // positives per (b, class)
__device__ int      g_bin[BB * CC * NN];     // per-(b,class) anchor index lists (51.2MB)

// Single IoU routine, __noinline__ so ALL kernels call the SAME compiled code
// -> bit-identical values, which the lq equality test (iou == gt_max) needs.
// Op order mirrors the reference: cxcywh->xyxy, area from xyxy, clip, div.
// *_rn intrinsics prevent FMA contraction from changing rounding per call site.
__device__ __noinline__ float iou_ga(float4 g, float garea, float4 a) {
    float hw = 0.5f * a.z;             // exact (exponent shift)
    float hh = 0.5f * a.w;
    float ax1 = a.x - hw, ay1 = a.y - hh;
    float ax2 = a.x + hw, ay2 = a.y + hh;
    float aarea = __fmul_rn(__fsub_rn(ax2, ax1), __fsub_rn(ay2, ay1));
    float ltx = fmaxf(g.x, ax1), lty = fmaxf(g.y, ay1);
    float rbx = fminf(g.z, ax2), rby = fminf(g.w, ay2);
    float w = fmaxf(__fsub_rn(rbx, ltx), 0.0f);
    float h = fmaxf(__fsub_rn(rby, lty), 0.0f);
    float inter = __fmul_rn(w, h);
    float uni = __fsub_rn(__fadd_rn(garea, aarea), inter);
    return __fdiv_rn(inter, uni);
}

__device__ __forceinline__ bool better(float v1, int i1, float v2, int i2) {
    return (v1 > v2) || (v1 == v2 && i1 < i2);
}

// ---------------- K0: per-image setup ----------------
__global__ void k_setup(const int* __restrict__ tgt_labels,
                        const float* __restrict__ tgt_boxes) {
    int b = blockIdx.x, t = threadIdx.x;
    __shared__ int s_lab[GG];
    __shared__ int s_cnt[CC];
    __shared__ int s_start[CC + 1];
    if (t < CC) {
        s_cnt[t] = 0;
        g_bin_cursor[b * CC + t] = 0;
        g_poscnt[b * CC + t] = 0;
    }
    __syncthreads();
    for (int g = t; g < GG; g += blockDim.x) {
        int lab = tgt_labels[b * GG + g];
        s_lab[g] = lab;
        atomicAdd(&s_cnt[lab], 1);
        g_counts[b * GG + g] = 0;
        g_gt_max[b * GG + g] = ENC_NEG1;
        float4 bx = ((const float4*)tgt_boxes)[b * GG + g];
        float hw = 0.5f * bx.z, hh = 0.5f * bx.w;
        float4 xy = make_float4(bx.x - hw, bx.y - hh, bx.x + hw, bx.y + hh);
        g_gt_xyxy[b * GG + g] = xy;
        g_gt_area[b * GG + g] =
            __fmul_rn(__fsub_rn(xy.z, xy.x), __fsub_rn(xy.w, xy.y));
    }
    __syncthreads();
    if (t == 0) {
        int acc = 0;
        for (int c = 0; c < CC; c++) { s_start[c] = acc; acc += s_cnt[c]; }
        s_start[CC] = acc;
    }
    __syncthreads();
    if (t <= CC) g_gt_cls_start[b * (CC + 1) + t] = s_start[t];
    if (t < CC) {
        int pos = s_start[t];
        for (int g = 0; g < GG; g++)            // ascending g -> first-index tie-break
            if (s_lab[g] == t) g_gt_cls_list[b * GG + pos++] = g;
    }
}

// ---------------- K1: per-anchor max/argmax, gt_max, class bins ----------------
__global__ void k_passA(const float* __restrict__ anchors,
                        const int* __restrict__ prompt_inds) {
    int b = blockIdx.y;
    int n = blockIdx.x * 256 + threadIdx.x;
    __shared__ unsigned s_gmax[GG];
    for (int g = threadIdx.x; g < GG; g += 256) s_gmax[g] = ENC_NEG1;
    __syncthreads();
    if (n < NN) {
        float4 a = ((const float4*)anchors)[b * NN + n];
        int cls = prompt_inds[b * NN + n];
        int s = g_gt_cls_start[b * (CC + 1) + cls];
        int e = g_gt_cls_start[b * (CC + 1) + cls + 1];
        float best = -1.0f;
        int bestg = 0;
        for (int j = s; j < e; j++) {
            int g = g_gt_cls_list[b * GG + j];
            float v = iou_ga(g_gt_xyxy[b * GG + g], g_gt_area[b * GG + g], a);
            if (v > best) { best = v; bestg = g; }
            atomicMax(&s_gmax[g], encf(v));
        }
        g_anchor_max[b * NN + n] = best;
        g_anchor_gt[b * NN + n] = bestg;
        int p = atomicAdd(&g_bin_cursor[b * CC + cls], 1);
        g_bin[(b * CC + cls) * NN + p] = n;
    }
    __syncthreads();
    for (int g = threadIdx.x; g < GG; g += 256) {
        unsigned v = s_gmax[g];
        if (v != ENC_NEG1) atomicMax(&g_gt_max[b * GG + g], v);
    }
}

// ---------------- K2: positive flags + optimistic counts ----------------
__global__ void k_passB(const float* __restrict__ anchors,
                        const int* __restrict__ prompt_inds) {
    int b = blockIdx.y;
    int n = blockIdx.x * 256 + threadIdx.x;
    if (n >= NN) return;
    float am = g_anchor_max[b * NN + n];
    int cls = prompt_inds[b * NN + n];
    bool pos = false;
    if (am >= T_HIGH_F) {
        pos = true;
    } else if (am >= 0.0f) {
        float4 a = ((const float4*)anchors)[b * NN + n];
        int s = g_gt_cls_start[b * (CC + 1) + cls];
        int e = g_gt_cls_start[b * (CC + 1) + cls + 1];
        for (int j = s; j < e; j++) {
            int g = g_gt_cls_list[b * GG + j];
            unsigned gm = g_gt_max[b * GG + g];
            if (gm >= ENC_ZERO &&
                encf(iou_ga(g_gt_xyxy[b * GG + g], g_gt_area[b * GG + g], a)) == gm) {
                pos = true;
                break;
            }
        }
    }
    g_pos[b * NN + n] = pos ? 1 : 0;
    if (pos) {
        atomicAdd(&g_poscnt[b * CC + cls], 1);
        atomicAdd(&g_counts[b * GG + g_anchor_gt[b * NN + n]], 1);
    }
}

// ---------------- K3: MAX_POS fixup (rare path; ordered per-class rank) ----------------
__global__ void k_fixup(const int* __restrict__ prompt_inds) {
    int b = blockIdx.x / CC, c = blockIdx.x % CC;
    if (g_poscnt[b * CC + c] <= MAXPOS) return;   // common case: nothing to do
    int tid = threadIdx.x;
    int lane = tid & 31, wid = tid >> 5;
    __shared__ int s_w[8];
    __shared__ int s_R;
    if (tid == 0) s_R = 0;
    __syncthreads();
    for (int base = 0; base < NN; base += 256) {
        int n = base + tid;
        bool p = false;
        if (n < NN && prompt_inds[b * NN + n] == c && g_pos[b * NN + n]) p = true;
        unsigned m = __ballot_sync(0xffffffffu, p);
        if (lane == 0) s_w[wid] = __popc(m);
        __syncthreads();
        int pre = 0;
        for (int w = 0; w < wid; w++) pre += s_w[w];
        int tot = pre;
        for (int w = wid; w < 8; w++) tot += s_w[w];
        int rank = s_R + pre + __popc(m & ((1u << lane) - 1));
        if (p && rank >= MAXPOS)   // these were optimistically counted -> remove
            atomicSub(&g_counts[b * GG + g_anchor_gt[b * NN + n]], 1);
        __syncthreads();
        if (tid == 0) s_R += tot;
        __syncthreads();
    }
}

// ---------------- K4: per-gt top-4 over its class's anchor bin + output ----------------
__global__ void k_topk(const float* __restrict__ anchors,
                       const int* __restrict__ tgt_labels,
                       float* __restrict__ out) {
    int bg = blockIdx.x;
    int b = bg / GG, g = bg % GG;
    int tid = threadIdx.x;
    const int P = BB * GG * KK;
    int count = g_counts[b * GG + g];
    int kk = min(count, KK);
    if (kk <= 0) {
        if (tid < KK) {
            int o = (b * GG + g) * KK + tid;
            out[o] = -1.0f;
            out[P + o] = -1.0f;
            out[2 * P + o] = 0.0f;
            out[3 * P + o] = 0.0f;
        }
        return;
    }
    int cls = tgt_labels[b * GG + g];
    float4 gt = g_gt_xyxy[b * GG + g];
    float ga = g_gt_area[b * GG + g];
    int m = g_bin_cursor[b * CC + cls];
    const int* lst = &g_bin[(b * CC + cls) * NN];

    float v[KK];
    int id[KK];
#pragma unroll
    for (int k = 0; k < KK; k++) { v[k] = -1e30f; id[k] = 0x7fffffff; }

    for (int i = tid; i < m; i += 128) {
        int n = lst[i];
        float4 a = ((const float4*)anchors)[b * NN + n];
        float val = iou_ga(gt, ga, a);
        if (better(val, n, v[KK - 1], id[KK - 1])) {
            v[KK - 1] = val; id[KK - 1] = n;
#pragma unroll
            for (int k = KK - 2; k >= 0; k--) {
                if (better(v[k + 1], id[k + 1], v[k], id[k])) {
                    float tv = v[k]; int ti = id[k];
                    v[k] = v[k + 1]; id[k] = id[k + 1];
                    v[k + 1] = tv;  id[k + 1] = ti;
                }
            }
        }
    }

    __shared__ float sv[128 * KK];
    __shared__ int   si[128 * KK];
#pragma unroll
    for (int k = 0; k < KK; k++) { sv[tid * KK + k] = v[k]; si[tid * KK + k] = id[k]; }
    __syncthreads();

    for (int step = 64; step >= 1; step >>= 1) {
        if (tid < step) {
            float av[KK], bv[KK], rv[KK];
            int ai[KK], bi[KK], ri[KK];
#pragma unroll
            for (int k = 0; k < KK; k++) {
                av[k] = sv[tid * KK + k];          ai[k] = si[tid * KK + k];
                bv[k] = sv[(tid + step) * KK + k]; bi[k] = si[(tid + step) * KK + k];
            }
            int ia = 0, ib = 0;
#pragma unroll
            for (int k = 0; k < KK; k++) {
                if (better(av[ia], ai[ia], bv[ib], bi[ib])) {
                    rv[k] = av[ia]; ri[k] = ai[ia]; ia++;
                } else {
                    rv[k] = bv[ib]; ri[k] = bi[ib]; ib++;
                }
            }
#pragma unroll
            for (int k = 0; k < KK; k++) { sv[tid * KK + k] = rv[k]; si[tid * KK + k] = ri[k]; }
        }
        __syncthreads();
    }

    if (tid < KK) {
        int k = tid;
        int o = (b * GG + g) * KK + k;
        bool valid = (k < kk);
        out[o]         = valid ? (float)si[k] : -1.0f;
        out[P + o]     = valid ? (float)g    : -1.0f;
        out[2 * P + o] = valid ? 1.0f : 0.0f;
        out[3 * P + o] = valid ? sv[k] : 0.0f;
    }
}

// ---------------- launch ----------------
extern "C" void kernel_launch(void* const* d_in, const int* in_sizes, int n_in,
                              void* d_out, int out_size) {
    (void)in_sizes; (void)n_in; (void)out_size;
    const float* anchors     = (const float*)d_in[2];
    const int*   prompt_inds = (const int*)d_in[3];
    const int*   tgt_labels  = (const int*)d_in[4];
    const float* tgt_boxes   = (const float*)d_in[5];
    float* out = (float*)d_out;

    k_setup<<<BB, 256>>>(tgt_labels, tgt_boxes);
    dim3 gridA((NN + 255) / 256, BB);
    k_passA<<<gridA, 256>>>(anchors, prompt_inds);
    k_passB<<<gridA, 256>>>(anchors, prompt_inds);
    k_fixup<<<BB * CC, 256>>>(prompt_inds);
    k_topk<<<BB * GG, 128>>>(anchors, tgt_labels, out);
}